// round 10
// baseline (speedup 1.0000x reference)
#include <cuda_runtime.h>
#include <cuda_bf16.h>
#include <mma.h>
#include <cstdint>

using namespace nvcuda;
using u64 = unsigned long long;
#define FULL_MASK 0xFFFFFFFFu

constexpr int IN_DIM = 256;
constexpr int D = 32;
constexpr float LN_EPS = 1e-5f;

constexpr int TILE_RF   = 128;         // rf rows per block tile (nrf % 128 == 0)
constexpr int KH        = 128;         // k-half size
constexpr int ASTRIDE   = 136;         // bf16 elems per A row
constexpr int BSTRIDE   = 264;         // bf16 elems per B row (full K)
constexpr int THREADS1  = 256;

__device__ float g_scratch[65536 * 3 * 32];   // [rf][32] projection pre-bias

// smem byte offsets (kernel 1)
constexpr int OFF_AHI = 0;
constexpr int OFF_ALO = OFF_AHI + TILE_RF * ASTRIDE * 2;
constexpr int OFF_BHI = OFF_ALO + TILE_RF * ASTRIDE * 2;
constexpr int OFF_BLO = OFF_BHI + D * BSTRIDE * 2;
constexpr int SMEM1   = OFF_BLO + D * BSTRIDE * 2;           // 103424

__device__ __forceinline__ void split4(float4 v, uint2& hi, uint2& lo) {
    __nv_bfloat162 h01 = __floats2bfloat162_rn(v.x, v.y);
    __nv_bfloat162 h23 = __floats2bfloat162_rn(v.z, v.w);
    float lx = v.x - __low2float(h01),  ly = v.y - __high2float(h01);
    float lz = v.z - __low2float(h23),  lw = v.w - __high2float(h23);
    __nv_bfloat162 l01 = __floats2bfloat162_rn(lx, ly);
    __nv_bfloat162 l23 = __floats2bfloat162_rn(lz, lw);
    hi.x = *reinterpret_cast<uint32_t*>(&h01);
    hi.y = *reinterpret_cast<uint32_t*>(&h23);
    lo.x = *reinterpret_cast<uint32_t*>(&l01);
    lo.y = *reinterpret_cast<uint32_t*>(&l23);
}

// ================= kernel 1: projection GEMM (unchanged from R9) =================
__global__ __launch_bounds__(THREADS1, 2)
void proj_kernel(const float* __restrict__ f1, const float* __restrict__ f4,
                 const float* __restrict__ fD, const float* __restrict__ Wp,
                 int nrf, int ntiles)
{
    extern __shared__ char sm[];
    __nv_bfloat16* Ahi = reinterpret_cast<__nv_bfloat16*>(sm + OFF_AHI);
    __nv_bfloat16* Alo = reinterpret_cast<__nv_bfloat16*>(sm + OFF_ALO);
    __nv_bfloat16* Bhi = reinterpret_cast<__nv_bfloat16*>(sm + OFF_BHI);
    __nv_bfloat16* Blo = reinterpret_cast<__nv_bfloat16*>(sm + OFF_BLO);

    const int tid = threadIdx.x, w = tid >> 5;

    #pragma unroll
    for (int t = 0; t < 8; t++) {
        int i = tid + t * THREADS1;
        int n = i >> 6, c4 = i & 63;
        float4 v = reinterpret_cast<const float4*>(Wp)[i];
        uint2 hi, lo;
        split4(v, hi, lo);
        *reinterpret_cast<uint2*>(&Bhi[n * BSTRIDE + c4 * 4]) = hi;
        *reinterpret_cast<uint2*>(&Blo[n * BSTRIDE + c4 * 4]) = lo;
    }

    auto ldg_half = [&](int tile, int half, float4 (&buf)[16]) {
        #pragma unroll
        for (int t = 0; t < 16; t++) {
            int i = tid + t * THREADS1;
            int rf_l = i >> 5, c4 = i & 31;
            int rf_g = tile * TILE_RF + rf_l;
            int row = rf_g / 3, ft = rf_g - 3 * row;
            const float* src = (ft == 0) ? f1 : (ft == 1) ? f4 : fD;
            buf[t] = reinterpret_cast<const float4*>(src)[row * 64 + half * 32 + c4];
        }
    };
    auto cvt_half = [&](float4 (&buf)[16]) {
        #pragma unroll
        for (int t = 0; t < 16; t++) {
            int i = tid + t * THREADS1;
            int rf_l = i >> 5, c4 = i & 31;
            uint2 hi, lo;
            split4(buf[t], hi, lo);
            *reinterpret_cast<uint2*>(&Ahi[rf_l * ASTRIDE + c4 * 4]) = hi;
            *reinterpret_cast<uint2*>(&Alo[rf_l * ASTRIDE + c4 * 4]) = lo;
        }
    };

    float4 buf[16];
    int tile0 = blockIdx.x;
    if (tile0 < ntiles) ldg_half(tile0, 0, buf);
    __syncthreads();

    for (int tile = tile0; tile < ntiles; tile += gridDim.x) {
        wmma::fragment<wmma::accumulator, 16, 16, 16, float> C[2];
        wmma::fill_fragment(C[0], 0.f);
        wmma::fill_fragment(C[1], 0.f);
        wmma::fragment<wmma::matrix_a, 16, 16, 16, __nv_bfloat16, wmma::row_major> ah, al;
        wmma::fragment<wmma::matrix_b, 16, 16, 16, __nv_bfloat16, wmma::col_major> bh, bl;

        #pragma unroll
        for (int half = 0; half < 2; half++) {
            cvt_half(buf);
            if (half == 0) {
                ldg_half(tile, 1, buf);
            } else {
                int nt = tile + gridDim.x;
                if (nt < ntiles) ldg_half(nt, 0, buf);
            }
            __syncthreads();

            const __nv_bfloat16* Aw_h = Ahi + (w * 16) * ASTRIDE;
            const __nv_bfloat16* Aw_l = Alo + (w * 16) * ASTRIDE;
            const __nv_bfloat16* Bk_h = Bhi + half * KH;
            const __nv_bfloat16* Bk_l = Blo + half * KH;
            #pragma unroll
            for (int k = 0; k < KH / 16; k++) {
                wmma::load_matrix_sync(ah, Aw_h + k * 16, ASTRIDE);
                wmma::load_matrix_sync(al, Aw_l + k * 16, ASTRIDE);
                #pragma unroll
                for (int n = 0; n < 2; n++) {
                    wmma::load_matrix_sync(bh, Bk_h + n * 16 * BSTRIDE + k * 16, BSTRIDE);
                    wmma::load_matrix_sync(bl, Bk_l + n * 16 * BSTRIDE + k * 16, BSTRIDE);
                    wmma::mma_sync(C[n], ah, bh, C[n]);
                    wmma::mma_sync(C[n], al, bh, C[n]);
                    wmma::mma_sync(C[n], ah, bl, C[n]);
                }
            }
            __syncthreads();
        }

        int rf0 = tile * TILE_RF + w * 16;
        wmma::store_matrix_sync(g_scratch + (size_t)rf0 * 32,      C[0], 32, wmma::mem_row_major);
        wmma::store_matrix_sync(g_scratch + (size_t)rf0 * 32 + 16, C[1], 32, wmma::mem_row_major);
    }
}

// ================= kernel 2: epilogue v2 (warp-specialized, pipelined) =================
__device__ __forceinline__ void ffma2(u64& d, u64 a, u64 b) {
    asm("fma.rn.f32x2 %0, %1, %2, %0;" : "+l"(d) : "l"(a), "l"(b));
}
__device__ __forceinline__ float hsum2(u64 a, u64 b) {
    return __uint_as_float((unsigned)a) + __uint_as_float((unsigned)(a >> 32))
         + __uint_as_float((unsigned)b) + __uint_as_float((unsigned)(b >> 32));
}
__device__ __forceinline__ float wsum(float v) {
    v += __shfl_xor_sync(FULL_MASK, v, 16);
    v += __shfl_xor_sync(FULL_MASK, v, 8);
    v += __shfl_xor_sync(FULL_MASK, v, 4);
    v += __shfl_xor_sync(FULL_MASK, v, 2);
    v += __shfl_xor_sync(FULL_MASK, v, 1);
    return v;
}
// y[lane] = sum_d W[lane][d] * vec[d], W in regs, vec broadcast from smem
__device__ __forceinline__ float matvec(const u64 (&wsm)[16], const float* vec) {
    const ulonglong2* vp = reinterpret_cast<const ulonglong2*>(vec);
    u64 a0 = 0ull, a1 = 0ull;
    #pragma unroll
    for (int c = 0; c < 8; c++) {
        ulonglong2 xv = vp[c];
        ffma2(a0, wsm[2 * c],     xv.x);
        ffma2(a1, wsm[2 * c + 1], xv.y);
    }
    return hsum2(a0, a1);
}

__global__ __launch_bounds__(256, 3)
void epi_kernel(const float* __restrict__ bp,
                const float* __restrict__ ln_g, const float* __restrict__ ln_b,
                const float* __restrict__ Wq,  const float* __restrict__ bq,
                const float* __restrict__ Wk,  const float* __restrict__ bk,
                const float* __restrict__ Wv,  const float* __restrict__ bv,
                const float* __restrict__ Wo1, const float* __restrict__ bo1,
                const float* __restrict__ Wo2, const float* __restrict__ bo2,
                float* __restrict__ out, int B)
{
    __shared__ __align__(16) float xs[2][24][D];      // LN outputs (double buf)
    __shared__ __align__(16) float qkv[3][24][D];
    __shared__ __align__(16) float pooled[2][8][D];
    __shared__ __align__(16) float o1s[2][8][D];

    const int tid = threadIdx.x, lane = tid & 31, w = tid >> 5;

    // one matrix per warp, register-resident
    const float* Wsel = (w < 2) ? Wq : (w < 4) ? Wk : (w < 6) ? Wv : (w == 6) ? Wo1 : Wo2;
    const float* bsel = (w < 2) ? bq : (w < 4) ? bk : (w < 6) ? bv : (w == 6) ? bo1 : bo2;
    u64 wsm[16];
    {
        const u64* src = reinterpret_cast<const u64*>(Wsel + lane * D);
        #pragma unroll
        for (int c = 0; c < 16; c++) wsm[c] = src[c];
    }
    const float bsel_l = bsel[lane];
    const float bp_l  = bp [lane];
    const float g_l   = ln_g[lane];
    const float b_l   = ln_b[lane];

    // warps 0-5 own LN/attention rows: w0:{0,6}, w1:{1,7}, w2..5:{w}
    const int nrows = (w < 2) ? 2 : (w < 6 ? 1 : 0);
    int lr[2] = { w, 6 + w };

    const int stride = gridDim.x * 8;
    const int r0_0 = blockIdx.x * 8;
    if (r0_0 >= B) return;    // uniform per block

    auto do_ln = [&](int grow, int lrow, int buf) {
        #pragma unroll
        for (int s = 0; s < 3; s++) {
            float h = g_scratch[(size_t)(grow * 3 + s) * D + lane] + bp_l;
            h = fmaxf(h, 0.f);
            float mu  = wsum(h) * (1.f / 32.f);
            float dv  = h - mu;
            float var = wsum(dv * dv) * (1.f / 32.f);
            xs[buf][lrow * 3 + s][lane] = g_l * dv * rsqrtf(var + LN_EPS) + b_l;
        }
    };

    // prologue: LN for iteration 0 into xs[0]
    if (w < 6) {
        #pragma unroll
        for (int r = 0; r < 2; r++)
            if (r < nrows) do_ln(r0_0 + lr[r], lr[r], 0);
    }

    int buf = 0;
    bool first = true;
    int r0 = r0_0;
    for (; r0 < B; r0 += stride) {
        const bool has_next = (r0 + stride) < B;
        const int prv = buf ^ 1;

        __syncthreads();   // A: xs[buf] ready; o1s[prv] free; pooled[prv] ready (w6)

        // ---- phase 2 ----
        if (w < 6) {
            const int mat = w >> 1;
            const int rf0 = (w & 1) * 12;
            #pragma unroll 4
            for (int u = 0; u < 12; u++) {
                int rf = rf0 + u;
                qkv[mat][rf][lane] = matvec(wsm, xs[buf][rf]) + bsel_l;
            }
        } else if (w == 6 && !first) {
            #pragma unroll
            for (int r = 0; r < 8; r++)
                o1s[prv][r][lane] = fmaxf(matvec(wsm, pooled[prv][r]) + bsel_l, 0.f);
        }

        __syncthreads();   // B: qkv ready; o1s[prv] ready

        // ---- phase 3 ----
        if (w < 6) {
            #pragma unroll
            for (int r = 0; r < 2; r++) {
                if (r >= nrows) break;
                const int L = lr[r];
                float qv[3], kv[3], vv[3];
                #pragma unroll
                for (int ss = 0; ss < 3; ss++) {
                    qv[ss] = qkv[0][L * 3 + ss][lane];
                    kv[ss] = qkv[1][L * 3 + ss][lane];
                    vv[ss] = qkv[2][L * 3 + ss][lane];
                }
                const float scale = 0.17677669529663687f;   // 1/sqrt(32)
                float att[3][3];
                #pragma unroll
                for (int ss = 0; ss < 3; ss++)
                    #pragma unroll
                    for (int tt = 0; tt < 3; tt++)
                        att[ss][tt] = wsum(qv[ss] * kv[tt]) * scale;

                float pool = 0.f;
                #pragma unroll
                for (int ss = 0; ss < 3; ss++) {
                    float m  = fmaxf(att[ss][0], fmaxf(att[ss][1], att[ss][2]));
                    float e0 = __expf(att[ss][0] - m);
                    float e1 = __expf(att[ss][1] - m);
                    float e2 = __expf(att[ss][2] - m);
                    float ri = 1.f / (e0 + e1 + e2);
                    pool += (e0 * vv[0] + e1 * vv[1] + e2 * vv[2]) * ri;
                }
                pooled[buf][L][lane] = pool * (1.f / 3.f);

                if (has_next) do_ln(r0 + stride + L, L, buf ^ 1);
            }
        } else if (w == 7 && !first) {
            const int pr0 = r0 - stride;
            #pragma unroll
            for (int r = 0; r < 8; r++) {
                out[(size_t)(pr0 + r) * D + lane] =
                    matvec(wsm, o1s[prv][r]) + bsel_l + pooled[prv][r][lane];
            }
        }

        first = false;
        buf ^= 1;
    }

    // ---- epilogue: finish last iteration's O chain ----
    const int lbuf = buf ^ 1;              // buffer of last processed iteration
    const int lr0  = r0 - stride;          // its row base
    __syncthreads();
    if (w == 6) {
        #pragma unroll
        for (int r = 0; r < 8; r++)
            o1s[lbuf][r][lane] = fmaxf(matvec(wsm, pooled[lbuf][r]) + bsel_l, 0.f);
    }
    __syncthreads();
    if (w == 7) {
        #pragma unroll
        for (int r = 0; r < 8; r++)
            out[(size_t)(lr0 + r) * D + lane] =
                matvec(wsm, o1s[lbuf][r]) + bsel_l + pooled[lbuf][r][lane];
    }
}

// ================= launch =================
extern "C" void kernel_launch(void* const* d_in, const int* in_sizes, int n_in,
                              void* d_out, int out_size)
{
    const float* f1   = (const float*)d_in[0];
    const float* f4   = (const float*)d_in[1];
    const float* fD   = (const float*)d_in[2];
    const float* Wp   = (const float*)d_in[3];
    const float* bp   = (const float*)d_in[4];
    const float* ln_g = (const float*)d_in[5];
    const float* ln_b = (const float*)d_in[6];
    const float* Wq   = (const float*)d_in[7];
    const float* bq   = (const float*)d_in[8];
    const float* Wk   = (const float*)d_in[9];
    const float* bk   = (const float*)d_in[10];
    const float* Wv   = (const float*)d_in[11];
    const float* bv   = (const float*)d_in[12];
    const float* Wo1  = (const float*)d_in[13];
    const float* bo1  = (const float*)d_in[14];
    const float* Wo2  = (const float*)d_in[15];
    const float* bo2  = (const float*)d_in[16];

    const int B = in_sizes[0] / IN_DIM;
    const int nrf = B * 3;
    const int ntiles = (nrf + TILE_RF - 1) / TILE_RF;

    cudaFuncSetAttribute(proj_kernel, cudaFuncAttributeMaxDynamicSharedMemorySize, SMEM1);

    int grid1 = ntiles < 304 ? ntiles : 304;
    proj_kernel<<<grid1, THREADS1, SMEM1>>>(f1, f4, fD, Wp, nrf, ntiles);

    int grid2 = 456;                      // 3 blocks x 152 SMs, persistent
    if (grid2 > (B + 7) / 8) grid2 = (B + 7) / 8;
    epi_kernel<<<grid2, 256>>>(bp, ln_g, ln_b, Wq, bq, Wk, bk, Wv, bv,
                               Wo1, bo1, Wo2, bo2, (float*)d_out, B);
}